// round 9
// baseline (speedup 1.0000x reference)
#include <cuda_runtime.h>
#include <cstdint>

// Problem dims (fixed by the dataset)
#define N_  64
#define C_  256
#define T_  64
#define V_  50
#define H_  16
#define P_  10
#define TV  3200               // floats per (n,c) slab

#define CLUSTER_CTAS 16
#define SLABS        16        // slabs per CTA (one per warp)
#define THREADS      512       // 16 warps

// Dynamic smem layout (float offsets):
//  [0, 51200)           xbuf: 16 slabs x 3200
//  [51200, 51520)       partials: avg[p*16+lc] (160) then max (160)
//  [51520, 51680)       hbuf: h[p*16+i] (160)
//  [51680, 56800)       UNION (5120 floats):
//     phase1: colscratch  per warp 100 floats (16*100=1600)
//     phase3: gather gAvg[10][256] (2560) + gMax[10][256] (2560)
//     phase5: tab float2[16][50] (3200 floats) + gt[16][10] (160)
#define OFF_PART   51200
#define OFF_H      51520
#define OFF_U      51680
#define SMEM_FLOATS (OFF_U + 5120)
#define SMEM_BYTES  (SMEM_FLOATS * 4)      // 227,200 B

// output column j -> input column v (concat order of PARTS)
__constant__ int c_cmap[V_] = {
    0,1,2,3,20,
    8,9,10,11,23,24,
    16,17,18,19,
    4,5,6,7,21,22,
    12,13,14,15,
    25,26,27,28,45,
    33,34,35,36,48,49,
    41,42,43,44,
    29,30,31,32,46,47,
    37,38,39,40
};
// output column j -> partition
__constant__ int c_pmap[V_] = {
    0,0,0,0,0,
    1,1,1,1,1,1,
    2,2,2,2,
    3,3,3,3,3,3,
    4,4,4,4,
    5,5,5,5,5,
    6,6,6,6,6,6,
    7,7,7,7,
    8,8,8,8,8,8,
    9,9,9,9
};
// partition -> member input columns (padded to 6) and sizes
__constant__ int c_pvs[P_ * 6] = {
    0,1,2,3,20,0,
    8,9,10,11,23,24,
    16,17,18,19,0,0,
    4,5,6,7,21,22,
    12,13,14,15,0,0,
    25,26,27,28,45,0,
    33,34,35,36,48,49,
    41,42,43,44,0,0,
    29,30,31,32,46,47,
    37,38,39,40,0,0
};
__constant__ int c_psize[P_] = {5,6,4,6,4,5,6,4,6,4};

__device__ __forceinline__ uint32_t smem_u32(const void* p) {
    uint32_t a;
    asm("{ .reg .u64 t; cvta.to.shared.u64 t, %1; cvt.u32.u64 %0, t; }"
        : "=r"(a) : "l"(p));
    return a;
}

extern __shared__ float smem[];

// ---------------------------------------------------------------------------
// One 16-CTA cluster per batch n. CTA rank owns channels rank*16..rank*16+15,
// one warp per channel slab. x is read from DRAM exactly once.
// ---------------------------------------------------------------------------
__global__ void __launch_bounds__(THREADS, 1) __cluster_dims__(CLUSTER_CTAS, 1, 1)
fused_cluster_kernel(const float* __restrict__ x,
                     const float* __restrict__ W1, const float* __restrict__ b1,
                     const float* __restrict__ W2, const float* __restrict__ b2,
                     float* __restrict__ out)
{
    const int tid  = threadIdx.x;
    const int w    = tid >> 5;
    const int lane = tid & 31;
    const int rank = blockIdx.x & (CLUSTER_CTAS - 1);
    const int n    = blockIdx.x >> 4;
    const int c    = rank * SLABS + w;           // channel of this warp's slab
    const size_t nc = (size_t)n * C_ + c;

    // ---- Phase 1: stream slab GMEM -> smem, accumulating per-column sum/max
    if (lane < 25) {
        const float2* px = (const float2*)x + nc * (TV / 2) + lane;
        float2* xs = (float2*)smem + (size_t)w * (TV / 2) + lane;
        float sx = 0.f, sy = 0.f;
        float mx = -3.402823466e+38f, my = -3.402823466e+38f;
#pragma unroll 8
        for (int r = 0; r < T_; ++r) {
            float2 v = px[r * 25];
            xs[r * 25] = v;
            sx += v.x;             sy += v.y;
            mx = fmaxf(mx, v.x);   my = fmaxf(my, v.y);
        }
        float* cS = smem + OFF_U + w * 100;      // [0..49] sums, [50..99] maxes
        cS[2 * lane]      = sx;   cS[2 * lane + 1]      = sy;
        cS[50 + 2 * lane] = mx;   cS[50 + 2 * lane + 1] = my;
    }
    __syncwarp();

    // per-part combine -> publish partials for this CTA's 16 channels
    if (lane < P_) {
        const float* cS = smem + OFF_U + w * 100;
        const int sz = c_psize[lane];
        float s3 = 0.f, m3 = -3.402823466e+38f;
        for (int j = 0; j < sz; ++j) {
            const int vv = c_pvs[lane * 6 + j];
            s3 += cS[vv];
            m3 = fmaxf(m3, cS[50 + vv]);
        }
        smem[OFF_PART +       lane * SLABS + w] = s3 / (float)(T_ * sz);
        smem[OFF_PART + 160 + lane * SLABS + w] = m3;
    }

    // ---- Cluster barrier: all partials visible cluster-wide
    asm volatile("barrier.cluster.arrive.aligned;" ::: "memory");
    asm volatile("barrier.cluster.wait.aligned;"   ::: "memory");

    // ---- Phase 3: gather all 16 CTAs' partials into local gAvg/gMax
    {
        const uint32_t part_local = smem_u32(smem + OFF_PART);
        if (tid < 320) {
            const int isMax = (tid >= 160);
            const int t2 = isMax ? tid - 160 : tid;
            const int p  = t2 >> 4;
            const int lc = t2 & 15;
#pragma unroll
            for (int r = 0; r < CLUSTER_CTAS; ++r) {
                uint32_t ra;
                asm("mapa.shared::cluster.u32 %0, %1, %2;"
                    : "=r"(ra) : "r"(part_local + tid * 4), "r"(r));
                float v;
                asm volatile("ld.shared::cluster.f32 %0, [%1];"
                             : "=f"(v) : "r"(ra));
                smem[OFF_U + isMax * 2560 + p * 256 + r * SLABS + lc] = v;
            }
        }
    }
    __syncthreads();

    // ---- Phase 4: h[p][i] = relu(W1[p,i]·avg[p]+b1) + relu(W1[p,i]·max[p]+b1)
    // warp w computes pairs idx = w + 16k  (p = k, i = w)
#pragma unroll
    for (int k = 0; k < P_; ++k) {
        const int p = k, i = w;
        const float* w1 = W1 + ((size_t)p * H_ + i) * C_;
        float da = 0.f, dm = 0.f;
#pragma unroll
        for (int kk = 0; kk < 8; ++kk) {
            const int cc = lane + 32 * kk;
            const float wv = w1[cc];
            da += wv * smem[OFF_U +        p * 256 + cc];
            dm += wv * smem[OFF_U + 2560 + p * 256 + cc];
        }
#pragma unroll
        for (int off = 16; off > 0; off >>= 1) {
            da += __shfl_down_sync(0xffffffffu, da, off);
            dm += __shfl_down_sync(0xffffffffu, dm, off);
        }
        if (lane == 0) {
            const float bb = b1[p * H_ + i];
            smem[OFF_H + p * H_ + i] = fmaxf(da + bb, 0.f) + fmaxf(dm + bb, 0.f);
        }
    }
    __syncthreads();        // h done; gather region now reusable

    // ---- Phase 5: per-slab gates + per-output-column table
    float2* tab = (float2*)(smem + OFF_U);           // [16][50]
    float*  gt  = smem + OFF_U + 3200;               // [16][10]
    if (lane < P_) {
        const int p = lane;
        const float* w2 = W2 + ((size_t)p * C_ + c) * H_;
        float acc = 2.f * b2[p * C_ + c];
#pragma unroll
        for (int i = 0; i < H_; ++i)
            acc += w2[i] * smem[OFF_H + p * H_ + i];
        gt[w * P_ + p] = 1.f / (1.f + __expf(-acc));
    }
    __syncwarp();
    if (lane < 25) {
#pragma unroll
        for (int q = 0; q < 2; ++q) {
            const int j = lane + 25 * q;
            float2 t;
            t.x = gt[w * P_ + c_pmap[j]];
            t.y = __int_as_float(c_cmap[j] - j);
            tab[w * V_ + j] = t;
        }
    }
    __syncwarp();

    // ---- Phase 6: scale from smem, coalesced streaming stores
    {
        const float* xs = smem + (size_t)w * TV;
        float* ob = out + nc * TV;
        int col = lane;                       // (lane + 32m) % 50, incremental
#pragma unroll 4
        for (int m = 0; m < 100; ++m) {
            const int jj = lane + 32 * m;
            const float2 t = tab[w * V_ + col];
            __stcs(&ob[jj], xs[jj + __float_as_int(t.y)] * t.x);
            col += 32;
            if (col >= V_) col -= V_;
        }
    }

    // keep smem alive until all peers finished their DSMEM reads
    asm volatile("barrier.cluster.arrive.aligned;" ::: "memory");
    asm volatile("barrier.cluster.wait.aligned;"   ::: "memory");
}

// ---------------------------------------------------------------------------
extern "C" void kernel_launch(void* const* d_in, const int* in_sizes, int n_in,
                              void* d_out, int out_size)
{
    const float* x  = (const float*)d_in[0];
    const float* W1 = (const float*)d_in[1];
    const float* b1 = (const float*)d_in[2];
    const float* W2 = (const float*)d_in[3];
    const float* b2 = (const float*)d_in[4];
    float* out = (float*)d_out;

    static int configured = 0;
    if (!configured) {
        cudaFuncSetAttribute(fused_cluster_kernel,
                             cudaFuncAttributeNonPortableClusterSizeAllowed, 1);
        cudaFuncSetAttribute(fused_cluster_kernel,
                             cudaFuncAttributeMaxDynamicSharedMemorySize,
                             SMEM_BYTES);
        configured = 1;
    }

    cudaLaunchConfig_t cfg = {};
    cfg.gridDim  = dim3(N_ * CLUSTER_CTAS, 1, 1);    // 1024 CTAs = 64 clusters
    cfg.blockDim = dim3(THREADS, 1, 1);
    cfg.dynamicSmemBytes = SMEM_BYTES;
    cudaLaunchAttribute attrs[1];
    attrs[0].id = cudaLaunchAttributeClusterDimension;
    attrs[0].val.clusterDim = {CLUSTER_CTAS, 1, 1};
    cfg.attrs = attrs;
    cfg.numAttrs = 1;

    cudaLaunchKernelEx(&cfg, fused_cluster_kernel, x, W1, b1, W2, b2, out);
}

// round 10
// speedup vs baseline: 1.8085x; 1.8085x over previous
#include <cuda_runtime.h>
#include <cstdint>

// Problem dims (fixed by the dataset)
#define N_  64
#define C_  256
#define T_  64
#define V_  50
#define H_  16
#define P_  10
#define TV  (T_ * V_)          // 3200 floats per (n,c) slab

#define HALF_NC  (N_ * C_ / 2)     // 8192 slabs per half (105 MB)

// output column j -> input column v (concat order of PARTS)
__constant__ int c_cmap[V_] = {
    0,1,2,3,20,
    8,9,10,11,23,24,
    16,17,18,19,
    4,5,6,7,21,22,
    12,13,14,15,
    25,26,27,28,45,
    33,34,35,36,48,49,
    41,42,43,44,
    29,30,31,32,46,47,
    37,38,39,40
};
// output column j -> partition
__constant__ int c_pmap[V_] = {
    0,0,0,0,0,
    1,1,1,1,1,1,
    2,2,2,2,
    3,3,3,3,3,3,
    4,4,4,4,
    5,5,5,5,5,
    6,6,6,6,6,6,
    7,7,7,7,
    8,8,8,8,8,8,
    9,9,9,9
};
// partition -> member input columns (padded to 6) and sizes
__constant__ int c_pvs[P_ * 6] = {
    0,1,2,3,20,0,
    8,9,10,11,23,24,
    16,17,18,19,0,0,
    4,5,6,7,21,22,
    12,13,14,15,0,0,
    25,26,27,28,45,0,
    33,34,35,36,48,49,
    41,42,43,44,0,0,
    29,30,31,32,46,47,
    37,38,39,40,0,0
};
__constant__ int c_psize[P_] = {5,6,4,6,4,5,6,4,6,4};

// Scratch (alloc-free rule: __device__ globals). Layout: [n][p][c]
__device__ float g_avg [N_ * P_ * C_];
__device__ float g_max [N_ * P_ * C_];
__device__ float g_gate[N_ * P_ * C_];

// ---------------------------------------------------------------------------
// Kernel 1: per-(n,c) sum+max over (t, v in part) for all 10 parts.
// One WARP per (n,c) slab; lanes 0..24 own a column-pair as float2.
// (Best measured reduce variant.)
// ---------------------------------------------------------------------------
__global__ __launch_bounds__(256)
void reduce_kernel(const float2* __restrict__ x2, int nc0)
{
    __shared__ float cs [8][V_ + 2];
    __shared__ float cmx[8][V_ + 2];

    const int warp = threadIdx.x >> 5;
    const int lane = threadIdx.x & 31;
    const int nc   = nc0 + blockIdx.x * 8 + warp;    // n*C_ + c

    if (lane < 25) {
        const float2* p = x2 + (size_t)nc * (TV / 2) + lane;
        float sx = 0.f, sy = 0.f;
        float mx = -3.402823466e+38f, my = -3.402823466e+38f;
#pragma unroll 8
        for (int r = 0; r < T_; ++r) {
            float2 v = p[r * 25];
            sx += v.x;             sy += v.y;
            mx = fmaxf(mx, v.x);   my = fmaxf(my, v.y);
        }
        cs [warp][2 * lane]     = sx;
        cs [warp][2 * lane + 1] = sy;
        cmx[warp][2 * lane]     = mx;
        cmx[warp][2 * lane + 1] = my;
    }
    __syncwarp();

    if (lane < P_) {
        const int sz = c_psize[lane];
        float s3 = 0.f, m3 = -3.402823466e+38f;
        for (int j = 0; j < sz; ++j) {
            const int vv = c_pvs[lane * 6 + j];
            s3 += cs[warp][vv];
            m3 = fmaxf(m3, cmx[warp][vv]);
        }
        const int n = nc >> 8;      // C_ = 256
        const int c = nc & 255;
        const size_t o = ((size_t)n * P_ + lane) * C_ + c;
        g_avg[o] = s3 / (float)(T_ * sz);
        g_max[o] = m3;
    }
}

// ---------------------------------------------------------------------------
// Kernel 2: gate[n,p,c] = sigmoid( W2 @ (relu(W1@avg+b1)+relu(W1@mx+b1)) + 2*b2 )
// One block per (n,p), 256 threads.
// ---------------------------------------------------------------------------
__global__ __launch_bounds__(C_)
void gate_kernel(const float* __restrict__ W1, const float* __restrict__ b1,
                 const float* __restrict__ W2, const float* __restrict__ b2)
{
    const int np = blockIdx.x;
    const int n  = np / P_;
    const int p  = np % P_;
    const int tid = threadIdx.x;

    __shared__ float sa[C_];
    __shared__ float sx[C_];
    __shared__ float hs[H_];

    const size_t base = ((size_t)n * P_ + p) * C_;
    sa[tid] = g_avg[base + tid];
    sx[tid] = g_max[base + tid];
    __syncthreads();

    const int w = tid >> 5;     // warp 0..7
    const int l = tid & 31;

#pragma unroll
    for (int ii = 0; ii < 2; ++ii) {
        const int i = w + 8 * ii;
        const float* w1 = W1 + ((size_t)p * H_ + i) * C_;
        float da = 0.f, dm = 0.f;
#pragma unroll
        for (int k = 0; k < 8; ++k) {
            const int c = l + 32 * k;
            const float wv = w1[c];
            da += wv * sa[c];
            dm += wv * sx[c];
        }
#pragma unroll
        for (int off = 16; off > 0; off >>= 1) {
            da += __shfl_down_sync(0xffffffffu, da, off);
            dm += __shfl_down_sync(0xffffffffu, dm, off);
        }
        if (l == 0) {
            const float bb = b1[p * H_ + i];
            hs[i] = fmaxf(da + bb, 0.f) + fmaxf(dm + bb, 0.f);
        }
    }
    __syncthreads();

    const float* w2 = W2 + ((size_t)p * C_ + tid) * H_;
    float acc = 2.f * b2[p * C_ + tid];
#pragma unroll
    for (int k = 0; k < H_; ++k)
        acc += w2[k] * hs[k];

    g_gate[base + tid] = 1.f / (1.f + __expf(-acc));
}

// ---------------------------------------------------------------------------
// Kernel 3: out[n,c,t,j] = x[n,c,t,cmap[j]] * gate[n, pmap[j], c]
// smem-staged float4 reads; block order optionally reversed within the
// assigned half so the most-recently-cached slabs are consumed first.
// Streaming stores protect the L2-resident x half.
// ---------------------------------------------------------------------------
__global__ __launch_bounds__(256)
void scale_kernel(const float4* __restrict__ x4, float* __restrict__ out,
                  int nc0, int reverse)
{
    __shared__ float4 sh4[TV / 4];          // 12.8 KB
    __shared__ float2 tab[V_ + 2];          // {gate, int_as_float(cmap[j]-j)}
    float* sh = (float*)sh4;

    const int bid = reverse ? (HALF_NC - 1 - blockIdx.x) : blockIdx.x;
    const int nc  = nc0 + bid;
    const int tid = threadIdx.x;
    const int n = nc >> 8;
    const int c = nc & 255;

    const float4* xb = x4  + (size_t)nc * (TV / 4);
    float*        ob = out + (size_t)nc * TV;

    // Phase A: coalesced float4 loads into shared; threads <50 stage table
#pragma unroll
    for (int k = 0; k < 3; ++k)
        sh4[tid + 256 * k] = xb[tid + 256 * k];
    if (tid < 32)
        sh4[tid + 768] = xb[tid + 768];
    if (tid < V_) {
        const int j = tid;
        float2 t;
        t.x = g_gate[((size_t)n * P_ + c_pmap[j]) * C_ + c];
        t.y = __int_as_float(c_cmap[j] - j);
        tab[j] = t;
    }
    __syncthreads();

    // Phase B: lane-consecutive elements jj = tid + 256*m (3200 = 12*256+128)
    int col = tid % V_;                 // output column of element tid
#pragma unroll
    for (int m = 0; m < 13; ++m) {
        if (m < 12 || tid < 128) {
            const int jj = tid + 256 * m;
            const float2 t = tab[col];
            __stcs(&ob[jj], sh[jj + __float_as_int(t.y)] * t.x);
        }
        // advance column by 256 mod 50 = 6
        col += 6;
        if (col >= V_) col -= V_;
    }
}

// ---------------------------------------------------------------------------
extern "C" void kernel_launch(void* const* d_in, const int* in_sizes, int n_in,
                              void* d_out, int out_size)
{
    const float* x  = (const float*)d_in[0];
    const float* W1 = (const float*)d_in[1];
    const float* b1 = (const float*)d_in[2];
    const float* W2 = (const float*)d_in[3];
    const float* b2 = (const float*)d_in[4];
    float* out = (float*)d_out;

    // Half A then half B: when reduce(B) finishes, B (105 MB) is L2-resident.
    reduce_kernel<<<HALF_NC / 8, 256>>>((const float2*)x, 0);
    reduce_kernel<<<HALF_NC / 8, 256>>>((const float2*)x, HALF_NC);
    gate_kernel<<<N_ * P_, C_>>>(W1, b1, W2, b2);
    // Consume B first (L2 hits), newest slabs first; then A (DRAM).
    scale_kernel<<<HALF_NC, 256>>>((const float4*)x, out, HALF_NC, 1);
    scale_kernel<<<HALF_NC, 256>>>((const float4*)x, out, 0, 1);
}